// round 4
// baseline (speedup 1.0000x reference)
#include <cuda_runtime.h>

// GwcVolume: group-wise correlation cost volumes (lr + rl).
// Shapes (fixed by the problem): B=1, F=320, H=128, W=256, G=40, C=8, D=48.
//
// lr[g,d,h,w] = (w>=d)   * (1/C) * sum_c L[g*C+c,h,w] * R[g*C+c,h,w-d]
// rl[g,d,h,w] = (w<W-d)  * lr[g,d,h,w+d]            (identical values, shifted)
//
// One block per (g,h) row; 256 threads = one per w.
// L row in registers, R row in shared memory; each dot product computed once
// and stored to both volumes. All output elements (including zeros) written.

constexpr int F = 320;
constexpr int H = 128;
constexpr int W = 256;
constexpr int G = 40;
constexpr int C = 8;          // F / G
constexpr int D = 48;

__global__ __launch_bounds__(W, 8)
void gwc_volume_kernel(const float* __restrict__ L,
                       const float* __restrict__ R,
                       const int*   __restrict__ bins,
                       float*       __restrict__ out)
{
    const int h = blockIdx.x;     // 0..H-1
    const int g = blockIdx.y;     // 0..G-1
    const int w = threadIdx.x;    // 0..W-1

    __shared__ float Rsh[C][W];   // 8 KB
    __shared__ int   dsh[D];

    const long chanHW = (long)H * W;
    const long base   = (long)g * C * chanHW + (long)h * W + w;

    // Stage: L[:,w] -> registers, R[:,w] -> smem. Fully coalesced LDG,
    // each input byte read from DRAM exactly once kernel-wide.
    float Lreg[C];
#pragma unroll
    for (int c = 0; c < C; ++c) {
        Lreg[c]   = __ldg(L + base + (long)c * chanHW);
        Rsh[c][w] = __ldg(R + base + (long)c * chanHW);
    }
    if (w < D) dsh[w] = bins[w];
    __syncthreads();

    float* lr = out + (long)g * D * chanHW + (long)h * W;
    float* rl = lr + (long)G * D * chanHW;

    for (int i = 0; i < D; ++i) {
        const int  d   = dsh[i];
        const long off = (long)i * chanHW;

        if (w >= d) {
            float v = 0.f;
#pragma unroll
            for (int c = 0; c < C; ++c)
                v += Lreg[c] * Rsh[c][w - d];
            v *= (1.0f / (float)C);
            __stcs(lr + off + w, v);            // lr[g,i,h,w]
            __stcs(rl + off + (w - d), v);      // rl[g,i,h,w-d] = lr shifted
        } else {
            // Zero regions: lr for w < d, rl tail [W-d, W).
            __stcs(lr + off + w, 0.f);
            __stcs(rl + off + (W - d + w), 0.f);
        }
    }
}

extern "C" void kernel_launch(void* const* d_in, const int* in_sizes, int n_in,
                              void* d_out, int out_size)
{
    const float* Lf   = (const float*)d_in[0];   // features_left  [1,320,128,256] f32
    const float* Rf   = (const float*)d_in[1];   // features_right [1,320,128,256] f32
    const int*   bins = (const int*)  d_in[2];   // [48] int32

    dim3 grid(H, G);
    gwc_volume_kernel<<<grid, W>>>(Lf, Rf, bins, (float*)d_out);
}

// round 5
// speedup vs baseline: 1.0185x; 1.0185x over previous
#include <cuda_runtime.h>

// GwcVolume: group-wise correlation cost volumes (lr + rl).
// Shapes (fixed): B=1, F=320, H=128, W=256, G=40, C=8, D=48.
//
// lr[g,d,h,w]   = (w>=d)  * (1/C) * sum_c L[gC+c,h,w] * R[gC+c,h,w-d]
// rl[g,d,h,w']  = (w'<W-d)* lr[g,d,h,w'+d]   (same values, shifted)
//
// One block per (g,h) row; 256 threads = one per w.
// L row in registers (float2-packed), R row in shared memory (float2-packed).
// Branchless: idx = (w-d) & (W-1) places valid values AND the zero tails of
// both volumes with uniform warps (no divergence). Each dot product computed
// once, stored twice. Every output element written exactly once.

constexpr int H = 128;
constexpr int W = 256;
constexpr int G = 40;
constexpr int C = 8;          // channels per group
constexpr int C2 = C / 2;     // float2-packed channels
constexpr int D = 48;

__global__ __launch_bounds__(W, 8)
void gwc_volume_kernel(const float* __restrict__ L,
                       const float* __restrict__ R,
                       const int*   __restrict__ bins,
                       float*       __restrict__ out)
{
    const int h = blockIdx.x;     // 0..H-1
    const int g = blockIdx.y;     // 0..G-1
    const int w = threadIdx.x;    // 0..W-1

    __shared__ float2 Rsh[C2][W]; // 8 KB, channel pairs packed for LDS.64
    __shared__ int    dsh[D];

    const long chanHW = (long)H * W;
    const long base   = (long)g * C * chanHW + (long)h * W + w;

    // Stage inputs: fully coalesced, each input byte read from DRAM once.
    float2 Lreg[C2];
#pragma unroll
    for (int c2 = 0; c2 < C2; ++c2) {
        Lreg[c2].x   = __ldg(L + base + (long)(2 * c2)     * chanHW);
        Lreg[c2].y   = __ldg(L + base + (long)(2 * c2 + 1) * chanHW);
        float rx     = __ldg(R + base + (long)(2 * c2)     * chanHW);
        float ry     = __ldg(R + base + (long)(2 * c2 + 1) * chanHW);
        Rsh[c2][w]   = make_float2(rx, ry);
    }
    if (w < D) dsh[w] = bins[w];
    __syncthreads();

    float* __restrict__ lr = out + (long)g * D * chanHW + (long)h * W;
    float* __restrict__ rl = lr + (long)G * D * chanHW;

#pragma unroll 4
    for (int i = 0; i < D; ++i) {
        const int d   = dsh[i];
        const int idx = (w - d) & (W - 1);   // wrap: w>=d -> w-d ; w<d -> W-d+w

        // Dot product over 8 channels (4 x LDS.64, conflict-free).
        const float2 r0 = Rsh[0][idx];
        const float2 r1 = Rsh[1][idx];
        const float2 r2 = Rsh[2][idx];
        const float2 r3 = Rsh[3][idx];
        float v = Lreg[0].x * r0.x;
        v = fmaf(Lreg[0].y, r0.y, v);
        v = fmaf(Lreg[1].x, r1.x, v);
        v = fmaf(Lreg[1].y, r1.y, v);
        v = fmaf(Lreg[2].x, r2.x, v);
        v = fmaf(Lreg[2].y, r2.y, v);
        v = fmaf(Lreg[3].x, r3.x, v);
        v = fmaf(Lreg[3].y, r3.y, v);

        // w>=d: valid value; w<d: this thread writes the zero tails
        // (lr[w] for w<d, rl[W-d+w] == rl[idx]) — uniform warp, no divergence.
        const float val = (w >= d) ? v * (1.0f / (float)C) : 0.0f;

        const long off = (long)i * chanHW;
        __stcs(lr + off + w,   val);   // lr[g,i,h,w]
        __stcs(rl + off + idx, val);   // rl[g,i,h,(w-d) mod W]
    }
}

extern "C" void kernel_launch(void* const* d_in, const int* in_sizes, int n_in,
                              void* d_out, int out_size)
{
    const float* Lf   = (const float*)d_in[0];   // features_left  [1,320,128,256] f32
    const float* Rf   = (const float*)d_in[1];   // features_right [1,320,128,256] f32
    const int*   bins = (const int*)  d_in[2];   // [48] int32

    dim3 grid(H, G);
    gwc_volume_kernel<<<grid, W>>>(Lf, Rf, bins, (float*)d_out);
}